// round 2
// baseline (speedup 1.0000x reference)
#include <cuda_runtime.h>
#include <cstdint>

#define BB   512      // batch
#define LL   512      // leaves
#define EE   128      // emb
#define OPS  5
#define NI   511      // internal nodes
#define RPC  4        // batch rows per CTA

// scratch: all node embeddings [B][NI][E]  (~134 MB)
__device__ float g_nodes[(size_t)BB * NI * EE];

// ---------------- packed f32x2 helpers ----------------
__device__ __forceinline__ unsigned long long pack2(float lo, float hi) {
    unsigned long long r;
    asm("mov.b64 %0, {%1, %2};" : "=l"(r) : "f"(lo), "f"(hi));
    return r;
}
__device__ __forceinline__ void fma2(unsigned long long& d, unsigned long long a, unsigned long long b) {
    asm("fma.rn.f32x2 %0, %1, %2, %0;" : "+l"(d) : "l"(a), "l"(b));
}
__device__ __forceinline__ float2 unpack2(unsigned long long v) {
    float2 f;
    asm("mov.b64 {%0, %1}, %2;" : "=f"(f.x), "=f"(f.y) : "l"(v));
    return f;
}
__device__ __forceinline__ uint32_t smem_u32(const void* p) {
    uint32_t a;
    asm("{ .reg .u64 t; cvta.to.shared.u64 t, %1; cvt.u32.u64 %0, t; }" : "=r"(a) : "l"(p));
    return a;
}
// LDS.128 -> two b64 register pairs (two f32x2 operands)
__device__ __forceinline__ void lds128_pair(unsigned long long& a, unsigned long long& b, uint32_t addr) {
    asm volatile("ld.shared.v2.u64 {%0, %1}, [%2];" : "=l"(a), "=l"(b) : "r"(addr));
}

// ---------------- sequential recurrence ----------------
// 256 threads: n = tid & 127 (output column), h = tid >> 7 (K-half of 64).
// Each thread keeps its W_left / W_right column slice in registers as f32x2 pairs.
__global__ void __launch_bounds__(256, 1) recur_kernel(
    const float* __restrict__ emb,   // [B, L, E]
    const float* __restrict__ Ww,    // [2E, E]
    const float* __restrict__ Wb,    // [E]
    const int*   __restrict__ li,    // [NI]
    const int*   __restrict__ ri)    // [NI]
{
    __shared__ __align__(16) float cur[RPC][EE];
    __shared__ __align__(16) float leafs[2][RPC][EE];
    __shared__ float red[RPC][EE];
    __shared__ int ridx[NI + 1];

    const int t  = threadIdx.x;
    const int n  = t & 127;
    const int h  = t >> 7;          // 0 or 1
    const int b0 = blockIdx.x * RPC;

    // Load weight column slices into registers, packed along K.
    unsigned long long wl2[32], wr2[32];
#pragma unroll
    for (int k2 = 0; k2 < 32; k2++) {
        const int kk = h * 64 + 2 * k2;
        wl2[k2] = pack2(Ww[(size_t)kk * EE + n],        Ww[(size_t)(kk + 1) * EE + n]);
        wr2[k2] = pack2(Ww[(size_t)(EE + kk) * EE + n], Ww[(size_t)(EE + kk + 1) * EE + n]);
    }
    const float bias = Wb[n];

    // right-leaf indices into smem
    for (int j = t; j < NI; j += 256) ridx[j] = ri[j];
    if (t == 0) ridx[NI] = ri[0];   // dummy for prefetch overrun

    // init cur = leaf(left_idx[0]) for each row
    const int l0   = li[0];
    const int r_ld = t >> 6;              // row for loading (4 rows x 64 threads)
    const int c_ld = (t & 63) * 2;        // 2 floats per thread
    {
        const float2 v = *(const float2*)&emb[((size_t)(b0 + r_ld) * LL + l0) * EE + c_ld];
        cur[r_ld][c_ld]     = v.x;
        cur[r_ld][c_ld + 1] = v.y;
    }
    __syncthreads();

    // prefetch right leaf for step 0
    float2 lv = *(const float2*)&emb[((size_t)(b0 + r_ld) * LL + ridx[0]) * EE + c_ld];

    const uint32_t cur_base  = smem_u32(cur);
    const uint32_t leaf_base = smem_u32(leafs);

    for (int j = 0; j < NI; j++) {
        const int buf = j & 1;
        // commit prefetched leaf to smem, grab next index
        leafs[buf][r_ld][c_ld]     = lv.x;
        leafs[buf][r_ld][c_ld + 1] = lv.y;
        const int rnext = ridx[j + 1];
        __syncthreads();                                   // leafs[buf] + cur ready
        // prefetch leaf for step j+1 (consumed next iteration -> DRAM latency hidden)
        lv = *(const float2*)&emb[((size_t)(b0 + r_ld) * LL + rnext) * EE + c_ld];

        unsigned long long a0[RPC], a1[RPC];
#pragma unroll
        for (int r = 0; r < RPC; r++) {
            unsigned long long s0 = 0ull, s1 = 0ull;       // {0.f,0.f}
            const uint32_t xl = cur_base  + (uint32_t)((r * EE + h * 64) * 4);
            const uint32_t xr = leaf_base + (uint32_t)(((buf * RPC + r) * EE + h * 64) * 4);
#pragma unroll
            for (int k4 = 0; k4 < 16; k4++) {
                unsigned long long p0, p1;
                lds128_pair(p0, p1, xl + k4 * 16);
                fma2(s0, p0, wl2[2 * k4]);
                fma2(s1, p1, wl2[2 * k4 + 1]);
            }
#pragma unroll
            for (int k4 = 0; k4 < 16; k4++) {
                unsigned long long p0, p1;
                lds128_pair(p0, p1, xr + k4 * 16);
                fma2(s0, p0, wr2[2 * k4]);
                fma2(s1, p1, wr2[2 * k4 + 1]);
            }
            a0[r] = s0; a1[r] = s1;
        }

        if (h == 1) {
#pragma unroll
            for (int r = 0; r < RPC; r++) {
                const float2 f0 = unpack2(a0[r]);
                const float2 f1 = unpack2(a1[r]);
                red[r][n] = (f0.x + f0.y) + (f1.x + f1.y);
            }
        }
        __syncthreads();                                   // red ready
        if (h == 0) {
#pragma unroll
            for (int r = 0; r < RPC; r++) {
                const float2 f0 = unpack2(a0[r]);
                const float2 f1 = unpack2(a1[r]);
                const float v = (f0.x + f0.y) + (f1.x + f1.y) + red[r][n] + bias;
                cur[r][n] = v;
                g_nodes[((size_t)(b0 + r) * NI + j) * EE + n] = v;
            }
        }
        // next iteration's first __syncthreads orders cur writes vs reads
    }
}

// ---------------- parallel projection: op = node @ G_w + G_b ----------------
// one warp per (b, j) node; lane l owns node[4l..4l+3]
__global__ void __launch_bounds__(256) proj_kernel(
    const float* __restrict__ Gw,   // [E, OPS]
    const float* __restrict__ Gb,   // [OPS]
    float* __restrict__ out,        // [B, NI, OPS]
    int total)
{
    __shared__ float gws[EE * OPS];
    __shared__ float gbs[OPS];
    const int t = threadIdx.x;
    for (int i = t; i < EE * OPS; i += blockDim.x) gws[i] = Gw[i];
    if (t < OPS) gbs[t] = Gb[t];
    __syncthreads();

    const int warp = blockIdx.x * (blockDim.x >> 5) + (t >> 5);
    if (warp >= total) return;
    const int lane = t & 31;

    const float4 x = *(const float4*)&g_nodes[(size_t)warp * EE + lane * 4];
    const float* g = &gws[lane * 4 * OPS];

    float p[OPS];
#pragma unroll
    for (int o = 0; o < OPS; o++)
        p[o] = x.x * g[o] + x.y * g[OPS + o] + x.z * g[2 * OPS + o] + x.w * g[3 * OPS + o];

#pragma unroll
    for (int off = 16; off; off >>= 1)
#pragma unroll
        for (int o = 0; o < OPS; o++)
            p[o] += __shfl_xor_sync(0xFFFFFFFFu, p[o], off);

    if (lane == 0) {
        float* op = out + (size_t)warp * OPS;
#pragma unroll
        for (int o = 0; o < OPS; o++) op[o] = p[o] + gbs[o];
    }
}

// ---------------- labels tail ----------------
// Labels are int32 on device (JAX x64 disabled downcasts the reference's
// int64). mode 1: cast to float into a float-typed tail of NI elements.
// mode 2: widen to int64 raw into a tail of 2*NI float slots.
__global__ void tail_kernel(const int* __restrict__ labels, float* __restrict__ out, int mode)
{
    const int j = blockIdx.x * blockDim.x + threadIdx.x;
    if (j >= NI) return;
    const size_t base = (size_t)BB * NI * OPS;
    if (mode == 1) {
        out[base + j] = (float)labels[j];
    } else {
        ((long long*)(out + base))[j] = (long long)labels[j];
    }
}

extern "C" void kernel_launch(void* const* d_in, const int* in_sizes, int n_in,
                              void* d_out, int out_size)
{
    const float* emb    = (const float*)d_in[0];
    const float* Ww     = (const float*)d_in[1];
    const float* Wb     = (const float*)d_in[2];
    const float* Gw     = (const float*)d_in[3];
    const float* Gb     = (const float*)d_in[4];
    const int*   li     = (const int*)d_in[5];
    const int*   ri     = (const int*)d_in[6];
    const int*   labels = (const int*)d_in[7];
    float*       out    = (float*)d_out;

    recur_kernel<<<BB / RPC, 256>>>(emb, Ww, Wb, li, ri);

    const int total = BB * NI;                 // 261632 nodes
    proj_kernel<<<total / 8, 256>>>(Gw, Gb, out, total);   // 8 warps/block, divides exactly

    const long long base = (long long)BB * NI * OPS;
    const long long tail = (long long)out_size - base;
    if (tail == NI)          tail_kernel<<<2, 256>>>(labels, out, 1);
    else if (tail == 2 * NI) tail_kernel<<<2, 256>>>(labels, out, 2);
}